// round 12
// baseline (speedup 1.0000x reference)
#include <cuda_runtime.h>
#include <cuda_bf16.h>
#include <math.h>
#include <stdint.h>

#define BB 256
#define TT 512
#define FF 256
#define HH 256
#define GG 1024
#define MM (TT * BB)

// ---------------- device globals (no runtime allocation) --------------------
__device__ float g_xw[(size_t)MM * GG];             // 512 MB: xW1(+b1), [m][4H]
__device__ float g_z2w[(size_t)MM * GG];            // 512 MB: h1@W2, [t*B+b][4H]
__device__ __nv_bfloat16 g_xhi[(size_t)MM * FF];    // 64 MB, row m = t*B+b
__device__ __nv_bfloat16 g_xlo[(size_t)MM * FF];
__device__ __nv_bfloat16 g_h1hi[2 * BB * HH];       // layer-1 h ring [2][B][H]
__device__ __nv_bfloat16 g_h1lo[2 * BB * HH];
__device__ __nv_bfloat16 g_h2hi[2 * BB * HH];       // layer-2 h ring
__device__ __nv_bfloat16 g_h2lo[2 * BB * HH];
__device__ __nv_bfloat16 g_whi[FF * GG];            // W1 bf16 hi/lo
__device__ __nv_bfloat16 g_wlo[FF * GG];
__device__ float g_hlast[BB * HH];
// sync: per group (8 = 2 layers x 4 grps): cnt at [g*64], pub at [g*64+32]
__device__ unsigned g_sync[8 * 64];

// ---------------- helpers ----------------------------------------------------
__device__ __forceinline__ float sigf(float v) { return 1.0f / (1.0f + __expf(-v)); }

__device__ __forceinline__ uint32_t smem_u32(const void* p) {
    uint32_t a;
    asm("{ .reg .u64 t; cvta.to.shared.u64 t, %1; cvt.u32.u64 %0, t; }"
        : "=r"(a) : "l"(p));
    return a;
}
__device__ __forceinline__ void ldmA(uint32_t& a0, uint32_t& a1,
                                     uint32_t& a2, uint32_t& a3, uint32_t addr) {
    asm volatile("ldmatrix.sync.aligned.m8n8.x4.shared.b16 {%0,%1,%2,%3}, [%4];"
                 : "=r"(a0), "=r"(a1), "=r"(a2), "=r"(a3) : "r"(addr));
}
__device__ __forceinline__ void ldmB(uint32_t& b0, uint32_t& b1, uint32_t addr) {
    asm volatile("ldmatrix.sync.aligned.m8n8.x2.trans.shared.b16 {%0,%1}, [%2];"
                 : "=r"(b0), "=r"(b1) : "r"(addr));
}
__device__ __forceinline__ void mma_bf16(float* d, uint32_t a0, uint32_t a1,
                                         uint32_t a2, uint32_t a3,
                                         uint32_t b0, uint32_t b1) {
    asm volatile(
        "mma.sync.aligned.m16n8k16.row.col.f32.bf16.bf16.f32 "
        "{%0,%1,%2,%3}, {%4,%5,%6,%7}, {%8,%9}, {%0,%1,%2,%3};"
        : "+f"(d[0]), "+f"(d[1]), "+f"(d[2]), "+f"(d[3])
        : "r"(a0), "r"(a1), "r"(a2), "r"(a3), "r"(b0), "r"(b1));
}
__device__ __forceinline__ void split_bf16(float v, __nv_bfloat16& hi, __nv_bfloat16& lo) {
    hi = __float2bfloat16_rn(v);
    lo = __float2bfloat16_rn(v - __bfloat162float(hi));
}

// ---- split sync: producers add cnt; last arriver publishes; waiters poll pub.
__device__ __forceinline__ void grp_arrive(int gidx, unsigned step) {
    unsigned old;
    asm volatile("atom.add.release.gpu.u32 %0, [%1], 1;"
                 : "=r"(old) : "l"(&g_sync[gidx * 64]) : "memory");
    if (old == 16u * step - 1u) {
        asm volatile("st.release.gpu.u32 [%0], %1;"
                     :: "l"(&g_sync[gidx * 64 + 32]), "r"(step) : "memory");
    }
}
__device__ __forceinline__ void grp_waitpub(int gidx, unsigned step) {
    unsigned g;
    do {
        asm volatile("ld.acquire.gpu.u32 %0, [%1];"
                     : "=r"(g) : "l"(&g_sync[gidx * 64 + 32]) : "memory");
    } while (g < step);
}

__global__ void init_flags_kernel() {
    const int i = blockIdx.x * 256 + threadIdx.x;
    if (i < 8 * 64) g_sync[i] = 0;
}

// ---------------------------------------------------------------------------
// conv_x: x[B][T][F] fp32 -> xhi/xlo bf16 rows m = t*B+b.
// ---------------------------------------------------------------------------
__global__ void conv_x_kernel(const float* __restrict__ x,
                              __nv_bfloat16* __restrict__ xhi,
                              __nv_bfloat16* __restrict__ xlo)
{
    const int gid = blockIdx.x * 256 + threadIdx.x;
    const int m = gid >> 5;
    const int c = (gid & 31) * 8;
    const int b = m & (BB - 1);
    const int t = m >> 8;
    const float* src = x + ((size_t)b * TT + t) * FF + c;
    float4 v0 = *(const float4*)src;
    float4 v1 = *(const float4*)(src + 4);
    float vv[8] = {v0.x, v0.y, v0.z, v0.w, v1.x, v1.y, v1.z, v1.w};
    __nv_bfloat16 hi8[8], lo8[8];
#pragma unroll
    for (int j = 0; j < 8; j++) split_bf16(vv[j], hi8[j], lo8[j]);
    *(uint4*)(xhi + (size_t)m * FF + c) = *(uint4*)hi8;
    *(uint4*)(xlo + (size_t)m * FF + c) = *(uint4*)lo8;
}

__global__ void conv_w_kernel(const float* __restrict__ W,
                              __nv_bfloat16* __restrict__ whi,
                              __nv_bfloat16* __restrict__ wlo)
{
    const int i = (blockIdx.x * 256 + threadIdx.x) * 4;
    float4 v = *(const float4*)(W + i);
    float vv[4] = {v.x, v.y, v.z, v.w};
    __nv_bfloat16 hi4[4], lo4[4];
#pragma unroll
    for (int j = 0; j < 4; j++) split_bf16(vv[j], hi4[j], lo4[j]);
    *(uint2*)(whi + i) = *(uint2*)hi4;
    *(uint2*)(wlo + i) = *(uint2*)lo4;
}

// ---------------------------------------------------------------------------
// bf16-split MMA GEMM (proven): 128m x 64n, BK=32, 256 thr.
// ---------------------------------------------------------------------------
#define GA_STR 80
#define GB_STR 144
#define GS_AHI 0
#define GS_ALO (GS_AHI + 128 * GA_STR)
#define GS_BHI (GS_ALO + 128 * GA_STR)
#define GS_BLO (GS_BHI + 32 * GB_STR)
#define GS_TOT (GS_BLO + 32 * GB_STR)

__global__ void __launch_bounds__(256, 2)
gemm_bf16_kernel(const __nv_bfloat16* __restrict__ Ahi_g,
                 const __nv_bfloat16* __restrict__ Alo_g,
                 const __nv_bfloat16* __restrict__ Bhi_g,
                 const __nv_bfloat16* __restrict__ Blo_g,
                 const float* __restrict__ bias,
                 float* __restrict__ Cout)
{
    __shared__ char gsm[GS_TOT];
    const uint32_t sb = smem_u32(gsm);

    const int tid  = threadIdx.x;
    const int w    = tid >> 5;
    const int lane = tid & 31;
    const int n0 = blockIdx.x * 64;
    const int m0 = blockIdx.y * 128;
    const int wm = (w >> 1) * 32;
    const int wn = (w & 1) * 32;

    const int ar = tid >> 1;
    const int ac = (tid & 1) * 2;
    const size_t aoff = (size_t)(m0 + ar) * FF;
    const int br = tid >> 3;
    const int bc = tid & 7;

    uint4 pAh0 = *(const uint4*)(Ahi_g + aoff + (ac + 0) * 8);
    uint4 pAh1 = *(const uint4*)(Ahi_g + aoff + (ac + 1) * 8);
    uint4 pAl0 = *(const uint4*)(Alo_g + aoff + (ac + 0) * 8);
    uint4 pAl1 = *(const uint4*)(Alo_g + aoff + (ac + 1) * 8);
    uint4 pBh  = *(const uint4*)(Bhi_g + (size_t)br * GG + n0 + bc * 8);
    uint4 pBl  = *(const uint4*)(Blo_g + (size_t)br * GG + n0 + bc * 8);

    float acc[2][4][4];
#pragma unroll
    for (int mt = 0; mt < 2; mt++)
#pragma unroll
        for (int nt = 0; nt < 4; nt++)
#pragma unroll
            for (int q = 0; q < 4; q++) acc[mt][nt][q] = 0.f;

    const uint32_t aAddr = sb + GS_AHI + (wm + (lane & 15)) * GA_STR + (lane >> 4) * 16;
    const uint32_t bAddr = sb + GS_BHI + (lane & 15) * GB_STR + wn * 2;

    for (int kb = 0; kb < 8; kb++) {
        *(uint4*)(gsm + GS_AHI + ar * GA_STR + (ac + 0) * 16) = pAh0;
        *(uint4*)(gsm + GS_AHI + ar * GA_STR + (ac + 1) * 16) = pAh1;
        *(uint4*)(gsm + GS_ALO + ar * GA_STR + (ac + 0) * 16) = pAl0;
        *(uint4*)(gsm + GS_ALO + ar * GA_STR + (ac + 1) * 16) = pAl1;
        *(uint4*)(gsm + GS_BHI + br * GB_STR + bc * 16) = pBh;
        *(uint4*)(gsm + GS_BLO + br * GB_STR + bc * 16) = pBl;
        if (kb < 7) {
            const int k1 = (kb + 1) * 32;
            pAh0 = *(const uint4*)(Ahi_g + aoff + k1 + (ac + 0) * 8);
            pAh1 = *(const uint4*)(Ahi_g + aoff + k1 + (ac + 1) * 8);
            pAl0 = *(const uint4*)(Alo_g + aoff + k1 + (ac + 0) * 8);
            pAl1 = *(const uint4*)(Alo_g + aoff + k1 + (ac + 1) * 8);
            pBh  = *(const uint4*)(Bhi_g + (size_t)(k1 + br) * GG + n0 + bc * 8);
            pBl  = *(const uint4*)(Blo_g + (size_t)(k1 + br) * GG + n0 + bc * 8);
        }
        __syncthreads();

#pragma unroll
        for (int kc = 0; kc < 2; kc++) {
            uint32_t ah[2][4], al[2][4];
#pragma unroll
            for (int mt = 0; mt < 2; mt++) {
                const uint32_t a = aAddr + mt * 16 * GA_STR + kc * 32;
                ldmA(ah[mt][0], ah[mt][1], ah[mt][2], ah[mt][3], a);
                ldmA(al[mt][0], al[mt][1], al[mt][2], al[mt][3],
                     a + (GS_ALO - GS_AHI));
            }
            uint32_t bh[4][2], bl[4][2];
#pragma unroll
            for (int nt = 0; nt < 4; nt++) {
                const uint32_t b = bAddr + kc * 16 * GB_STR + nt * 16;
                ldmB(bh[nt][0], bh[nt][1], b);
                ldmB(bl[nt][0], bl[nt][1], b + (GS_BLO - GS_BHI));
            }
#pragma unroll
            for (int mt = 0; mt < 2; mt++)
#pragma unroll
                for (int nt = 0; nt < 4; nt++) {
                    mma_bf16(acc[mt][nt], ah[mt][0], ah[mt][1], ah[mt][2], ah[mt][3],
                             bh[nt][0], bh[nt][1]);
                    mma_bf16(acc[mt][nt], ah[mt][0], ah[mt][1], ah[mt][2], ah[mt][3],
                             bl[nt][0], bl[nt][1]);
                    mma_bf16(acc[mt][nt], al[mt][0], al[mt][1], al[mt][2], al[mt][3],
                             bh[nt][0], bh[nt][1]);
                }
        }
        __syncthreads();
    }

#pragma unroll
    for (int mt = 0; mt < 2; mt++) {
        const int mrow = m0 + wm + mt * 16 + (lane >> 2);
#pragma unroll
        for (int nt = 0; nt < 4; nt++) {
            const int n = n0 + wn + nt * 8 + (lane & 3) * 2;
            const float2 b2 = *(const float2*)(bias + n);
            float* o0 = Cout + (size_t)mrow * GG + n;
            float* o1 = Cout + (size_t)(mrow + 8) * GG + n;
            *(float2*)o0 = make_float2(acc[mt][nt][0] + b2.x, acc[mt][nt][1] + b2.y);
            *(float2*)o1 = make_float2(acc[mt][nt][2] + b2.x, acc[mt][nt][3] + b2.y);
        }
    }
}

// ---------------------------------------------------------------------------
// Fused pipelined LSTM (R11 topology + split sync + merged accumulators).
// L1 (bid<64), tau=0..512: stage h1(tau-1); dual MMA U1 (->z1) + W2 (->z2W).
// L2 (bid>=64), t=0..511: stage h2(t-1); single U2 MMA; z-init from z2W(t)+b2.
// ---------------------------------------------------------------------------
#define SA_STR 528
#define S_AHI 0
#define S_ALO 33792
#define S_BWH 67584
#define S_BWL 100352
#define S_BUH 133120
#define S_BUL 165888
#define S_Z   198656
#define ZST   36
#define S_TOT (S_Z + 64 * ZST * 4)

// Merged-acc dual pass: 3 split terms accumulate into ONE acc set per pass.
__device__ __forceinline__ void mma_dual(float acc1[2][2][4],
                                         float acc2[2][2][4],
                                         uint32_t aHi, uint32_t aLo,
                                         uint32_t bU, uint32_t bW,
                                         uint32_t bLoOff, int doW)
{
#pragma unroll
    for (int kc = 0; kc < 16; kc++) {
        uint32_t ah0, ah1, ah2, ah3, al0, al1, al2, al3;
        ldmA(ah0, ah1, ah2, ah3, aHi + kc * 32);
        ldmA(al0, al1, al2, al3, aLo + kc * 32);
#pragma unroll
        for (int gl = 0; gl < 2; gl++) {
#pragma unroll
            for (int j = 0; j < 2; j++) {
                const uint32_t bu = bU + gl * 8192 + j * 16 + kc * 512;
                uint32_t bh0, bh1, bl0, bl1;
                ldmB(bh0, bh1, bu);
                ldmB(bl0, bl1, bu + bLoOff);
                mma_bf16(acc1[gl][j], ah0, ah1, ah2, ah3, bh0, bh1);
                mma_bf16(acc1[gl][j], ah0, ah1, ah2, ah3, bl0, bl1);
                mma_bf16(acc1[gl][j], al0, al1, al2, al3, bh0, bh1);
                if (doW) {
                    const uint32_t bw = bW + gl * 8192 + j * 16 + kc * 512;
                    uint32_t wh0, wh1, wl0, wl1;
                    ldmB(wh0, wh1, bw);
                    ldmB(wl0, wl1, bw + bLoOff);
                    mma_bf16(acc2[gl][j], ah0, ah1, ah2, ah3, wh0, wh1);
                    mma_bf16(acc2[gl][j], ah0, ah1, ah2, ah3, wl0, wl1);
                    mma_bf16(acc2[gl][j], al0, al1, al2, al3, wh0, wh1);
                }
            }
        }
    }
}

__global__ void __launch_bounds__(256, 1)
fused_lstm_kernel(const float* __restrict__ xw1,
                  const float* __restrict__ U1,
                  const float* __restrict__ W2, const float* __restrict__ U2,
                  const float* __restrict__ b2,
                  float* __restrict__ z2w,
                  __nv_bfloat16* __restrict__ h1hi,
                  __nv_bfloat16* __restrict__ h1lo,
                  __nv_bfloat16* __restrict__ h2hi,
                  __nv_bfloat16* __restrict__ h2lo,
                  float* __restrict__ hlast)
{
    extern __shared__ char smem[];
    const uint32_t sb = smem_u32(smem);
    float* zs = (float*)(smem + S_Z);

    const int tid  = threadIdx.x;
    const int w    = tid >> 5;
    const int lane = tid & 31;
    const int layer = blockIdx.x >> 6;
    const int sub   = blockIdx.x & 63;
    const int grp   = sub >> 4;
    const int gm0   = grp * 64;
    const int hc0   = (sub & 15) * 16;
    const int msub  = w & 3;
    const int gp    = w >> 2;
    const int isEpi = (gp == 0);

    const int ownG = layer * 4 + grp;
    const int l1G  = grp;

    // ---- one-time B fills (bf16 hi/lo, [gate][k][16 hc]) ----
    {
        const float* Ua = layer ? U2 : U1;
        for (int i = tid; i < 4 * 256 * 2; i += 256) {
            const int g = i >> 9;
            const int k = (i >> 1) & 255;
            const int half = i & 1;
            const int co = g * HH + hc0 + half * 8;
            const uint32_t so = (uint32_t)(g * 8192 + k * 32 + half * 16);
            const float* src = Ua + (size_t)k * GG + co;
            __nv_bfloat16 h8[8], l8[8];
#pragma unroll
            for (int j = 0; j < 8; j++) split_bf16(src[j], h8[j], l8[j]);
            *(uint4*)(smem + S_BUH + so) = *(uint4*)h8;
            *(uint4*)(smem + S_BUL + so) = *(uint4*)l8;
        }
        if (layer == 0) {
            for (int i = tid; i < 4 * 256 * 2; i += 256) {
                const int g = i >> 9;
                const int k = (i >> 1) & 255;
                const int half = i & 1;
                const int co = g * HH + hc0 + half * 8;
                const uint32_t so = (uint32_t)(g * 8192 + k * 32 + half * 16);
                const float* src = W2 + (size_t)k * GG + co;
                __nv_bfloat16 h8[8], l8[8];
#pragma unroll
                for (int j = 0; j < 8; j++) split_bf16(src[j], h8[j], l8[j]);
                *(uint4*)(smem + S_BWH + so) = *(uint4*)h8;
                *(uint4*)(smem + S_BWL + so) = *(uint4*)l8;
            }
        }
    }

    const int r0 = msub * 16 + (lane >> 2);
    const int c  = (lane & 3) * 2;

    float biaf[4][2][2];
    if (layer && isEpi) {
#pragma unroll
        for (int g = 0; g < 4; g++)
#pragma unroll
            for (int j = 0; j < 2; j++) {
                const float2 bb = *(const float2*)(b2 + g * HH + hc0 + j * 8 + c);
                biaf[g][j][0] = bb.x;
                biaf[g][j][1] = bb.y;
            }
    }
    float2 xq[4][2][2];
    if (!layer && isEpi) {
#pragma unroll
        for (int rh = 0; rh < 2; rh++) {
            const float* xr = xw1 + (size_t)(gm0 + r0 + rh * 8) * GG;
#pragma unroll
            for (int g = 0; g < 4; g++)
#pragma unroll
                for (int j = 0; j < 2; j++)
                    xq[g][j][rh] = *(const float2*)(xr + g * HH + hc0 + j * 8 + c);
        }
    }

    float creg[8];
#pragma unroll
    for (int i = 0; i < 8; i++) creg[i] = 0.f;

    const uint32_t aHi = sb + S_AHI + (msub * 16 + (lane & 15)) * SA_STR
                        + (lane >> 4) * 16;
    const uint32_t aLo = aHi + (S_ALO - S_AHI);
    const uint32_t bU  = sb + S_BUH + gp * 2 * 8192 + (lane & 15) * 32;
    const uint32_t bW  = sb + S_BWH + gp * 2 * 8192 + (lane & 15) * 32;
    const uint32_t bLoOff = 32768;

    if (layer == 0) {
        // ===================== LAYER 1: tau = 0..512 =====================
        for (int t = 0; t <= TT; t++) {
            float acc1[2][2][4], acc2[2][2][4];
#pragma unroll
            for (int gl = 0; gl < 2; gl++)
#pragma unroll
                for (int j = 0; j < 2; j++)
#pragma unroll
                    for (int q = 0; q < 4; q++) {
                        acc1[gl][j][q] = 0.f;
                        acc2[gl][j][q] = 0.f;
                    }

            if (t > 0) {
                if (tid == 0) grp_waitpub(ownG, (unsigned)t);
                __syncthreads();
                const __nv_bfloat16* shi = h1hi + (size_t)((t - 1) & 1) * BB * HH;
                const __nv_bfloat16* slo = h1lo + (size_t)((t - 1) & 1) * BB * HH;
#pragma unroll
                for (int i = 0; i < 8; i++) {
                    const int id = tid + i * 256;
                    const int r  = id >> 5;
                    const int cc = id & 31;
                    const uint4 vh = *((const uint4*)(shi + (size_t)(gm0 + r) * HH) + cc);
                    const uint4 vl = *((const uint4*)(slo + (size_t)(gm0 + r) * HH) + cc);
                    *(uint4*)(smem + S_AHI + r * SA_STR + cc * 16) = vh;
                    *(uint4*)(smem + S_ALO + r * SA_STR + cc * 16) = vl;
                }
                __syncthreads();
                mma_dual(acc1, acc2, aHi, aLo, bU, bW, bLoOff, 1);

                // write z2W(t-1)
                float* zw = z2w + (size_t)(t - 1) * BB * GG;
#pragma unroll
                for (int gl = 0; gl < 2; gl++)
#pragma unroll
                    for (int j = 0; j < 2; j++)
#pragma unroll
                        for (int rh = 0; rh < 2; rh++) {
                            const int row = gm0 + r0 + rh * 8;
                            const int col = (gp * 2 + gl) * HH + hc0 + j * 8 + c;
                            *(float2*)(zw + (size_t)row * GG + col) =
                                make_float2(acc2[gl][j][rh * 2], acc2[gl][j][rh * 2 + 1]);
                        }
            }

            if (t < TT) {
                if (!isEpi) {
#pragma unroll
                    for (int gl = 0; gl < 2; gl++)
#pragma unroll
                        for (int j = 0; j < 2; j++) {
                            *(float2*)&zs[r0 * ZST + gl * 16 + j * 8 + c] =
                                make_float2(acc1[gl][j][0], acc1[gl][j][1]);
                            *(float2*)&zs[(r0 + 8) * ZST + gl * 16 + j * 8 + c] =
                                make_float2(acc1[gl][j][2], acc1[gl][j][3]);
                        }
                }
                asm volatile("bar.sync %0, 64;" :: "r"(1 + msub) : "memory");

                if (isEpi) {
                    float zgv[2][2][2], zov[2][2][2];
#pragma unroll
                    for (int j = 0; j < 2; j++)
#pragma unroll
                        for (int rh = 0; rh < 2; rh++) {
                            const float2 a = *(float2*)&zs[(r0 + rh * 8) * ZST + 0 + j * 8 + c];
                            const float2 b = *(float2*)&zs[(r0 + rh * 8) * ZST + 16 + j * 8 + c];
                            zgv[j][rh][0] = a.x; zgv[j][rh][1] = a.y;
                            zov[j][rh][0] = b.x; zov[j][rh][1] = b.y;
                        }
                    float hv[2][2][2];
#pragma unroll
                    for (int rh = 0; rh < 2; rh++)
#pragma unroll
                        for (int j = 0; j < 2; j++)
#pragma unroll
                            for (int cp = 0; cp < 2; cp++) {
                                const int q = rh * 2 + cp;
                                const float zi = acc1[0][j][q]  + (cp ? xq[0][j][rh].y : xq[0][j][rh].x);
                                const float zf = acc1[1][j][q]  + (cp ? xq[1][j][rh].y : xq[1][j][rh].x);
                                const float zg = zgv[j][rh][cp] + (cp ? xq[2][j][rh].y : xq[2][j][rh].x);
                                const float zo = zov[j][rh][cp] + (cp ? xq[3][j][rh].y : xq[3][j][rh].x);
                                const float ig = sigf(zi), fg = sigf(zf);
                                const float gg = __tanhf(zg), og = sigf(zo);
                                const int ci = rh * 4 + j * 2 + cp;
                                const float cn = fg * creg[ci] + ig * gg;
                                creg[ci] = cn;
                                hv[rh][j][cp] = og * __tanhf(cn);
                            }
                    __nv_bfloat16* dhi = h1hi + (size_t)(t & 1) * BB * HH;
                    __nv_bfloat16* dlo = h1lo + (size_t)(t & 1) * BB * HH;
#pragma unroll
                    for (int rh = 0; rh < 2; rh++) {
                        const int row = gm0 + r0 + rh * 8;
#pragma unroll
                        for (int j = 0; j < 2; j++) {
                            const int colb = hc0 + j * 8 + c;
                            __nv_bfloat16 h0h, h1h_, h0l, h1l_;
                            split_bf16(hv[rh][j][0], h0h, h0l);
                            split_bf16(hv[rh][j][1], h1h_, h1l_);
                            *(uint32_t*)(dhi + (size_t)row * HH + colb) =
                                (uint32_t)__bfloat16_as_ushort(h0h)
                                | ((uint32_t)__bfloat16_as_ushort(h1h_) << 16);
                            *(uint32_t*)(dlo + (size_t)row * HH + colb) =
                                (uint32_t)__bfloat16_as_ushort(h0l)
                                | ((uint32_t)__bfloat16_as_ushort(h1l_) << 16);
                        }
                    }
                }
            }

            __syncthreads();
            if (tid == 0) grp_arrive(ownG, (unsigned)(t + 1));

            if (isEpi && t + 1 < TT) {
#pragma unroll
                for (int rh = 0; rh < 2; rh++) {
                    const float* xr = xw1 + ((size_t)(t + 1) * BB + gm0 + r0 + rh * 8) * GG;
#pragma unroll
                    for (int g = 0; g < 4; g++)
#pragma unroll
                        for (int j = 0; j < 2; j++)
                            xq[g][j][rh] = *(const float2*)(xr + g * HH + hc0 + j * 8 + c);
                }
            }
        }
    } else {
        // ===================== LAYER 2: t = 0..511 =====================
        for (int t = 0; t < TT; t++) {
            float acc1[2][2][4], accD[2][2][4];
#pragma unroll
            for (int gl = 0; gl < 2; gl++)
#pragma unroll
                for (int j = 0; j < 2; j++)
#pragma unroll
                    for (int q = 0; q < 4; q++) acc1[gl][j][q] = 0.f;

            if (tid == 0) {
                grp_waitpub(l1G, (unsigned)(t + 2));
                if (t > 0) grp_waitpub(ownG, (unsigned)t);
            }
            __syncthreads();

            // z-init prefetch: z2w(t)
            float2 zq[4][2][2];
            if (isEpi) {
#pragma unroll
                for (int rh = 0; rh < 2; rh++) {
                    const float* zr = z2w + ((size_t)t * BB + gm0 + r0 + rh * 8) * GG;
#pragma unroll
                    for (int g = 0; g < 4; g++)
#pragma unroll
                        for (int j = 0; j < 2; j++)
                            zq[g][j][rh] = *(const float2*)(zr + g * HH + hc0 + j * 8 + c);
                }
            }

            if (t > 0) {
                const __nv_bfloat16* shi = h2hi + (size_t)((t - 1) & 1) * BB * HH;
                const __nv_bfloat16* slo = h2lo + (size_t)((t - 1) & 1) * BB * HH;
#pragma unroll
                for (int i = 0; i < 8; i++) {
                    const int id = tid + i * 256;
                    const int r  = id >> 5;
                    const int cc = id & 31;
                    const uint4 vh = *((const uint4*)(shi + (size_t)(gm0 + r) * HH) + cc);
                    const uint4 vl = *((const uint4*)(slo + (size_t)(gm0 + r) * HH) + cc);
                    *(uint4*)(smem + S_AHI + r * SA_STR + cc * 16) = vh;
                    *(uint4*)(smem + S_ALO + r * SA_STR + cc * 16) = vl;
                }
                __syncthreads();
                mma_dual(acc1, accD, aHi, aLo, bU, bW, bLoOff, 0);
            }

            if (!isEpi) {
#pragma unroll
                for (int gl = 0; gl < 2; gl++)
#pragma unroll
                    for (int j = 0; j < 2; j++) {
                        *(float2*)&zs[r0 * ZST + gl * 16 + j * 8 + c] =
                            make_float2(acc1[gl][j][0], acc1[gl][j][1]);
                        *(float2*)&zs[(r0 + 8) * ZST + gl * 16 + j * 8 + c] =
                            make_float2(acc1[gl][j][2], acc1[gl][j][3]);
                    }
            }
            asm volatile("bar.sync %0, 64;" :: "r"(1 + msub) : "memory");

            if (isEpi) {
                float zgv[2][2][2], zov[2][2][2];
#pragma unroll
                for (int j = 0; j < 2; j++)
#pragma unroll
                    for (int rh = 0; rh < 2; rh++) {
                        const float2 a = *(float2*)&zs[(r0 + rh * 8) * ZST + 0 + j * 8 + c];
                        const float2 b = *(float2*)&zs[(r0 + rh * 8) * ZST + 16 + j * 8 + c];
                        zgv[j][rh][0] = a.x; zgv[j][rh][1] = a.y;
                        zov[j][rh][0] = b.x; zov[j][rh][1] = b.y;
                    }
                float hv[2][2][2];
#pragma unroll
                for (int rh = 0; rh < 2; rh++)
#pragma unroll
                    for (int j = 0; j < 2; j++)
#pragma unroll
                        for (int cp = 0; cp < 2; cp++) {
                            const int q = rh * 2 + cp;
                            const float zi = acc1[0][j][q]  + (cp ? zq[0][j][rh].y : zq[0][j][rh].x) + biaf[0][j][cp];
                            const float zf = acc1[1][j][q]  + (cp ? zq[1][j][rh].y : zq[1][j][rh].x) + biaf[1][j][cp];
                            const float zg = zgv[j][rh][cp] + (cp ? zq[2][j][rh].y : zq[2][j][rh].x) + biaf[2][j][cp];
                            const float zo = zov[j][rh][cp] + (cp ? zq[3][j][rh].y : zq[3][j][rh].x) + biaf[3][j][cp];
                            const float ig = sigf(zi), fg = sigf(zf);
                            const float gg = __tanhf(zg), og = sigf(zo);
                            const int ci = rh * 4 + j * 2 + cp;
                            const float cn = fg * creg[ci] + ig * gg;
                            creg[ci] = cn;
                            hv[rh][j][cp] = og * __tanhf(cn);
                        }
                __nv_bfloat16* dhi = h2hi + (size_t)(t & 1) * BB * HH;
                __nv_bfloat16* dlo = h2lo + (size_t)(t & 1) * BB * HH;
#pragma unroll
                for (int rh = 0; rh < 2; rh++) {
                    const int row = gm0 + r0 + rh * 8;
#pragma unroll
                    for (int j = 0; j < 2; j++) {
                        const int colb = hc0 + j * 8 + c;
                        __nv_bfloat16 h0h, h1h_, h0l, h1l_;
                        split_bf16(hv[rh][j][0], h0h, h0l);
                        split_bf16(hv[rh][j][1], h1h_, h1l_);
                        *(uint32_t*)(dhi + (size_t)row * HH + colb) =
                            (uint32_t)__bfloat16_as_ushort(h0h)
                            | ((uint32_t)__bfloat16_as_ushort(h1h_) << 16);
                        *(uint32_t*)(dlo + (size_t)row * HH + colb) =
                            (uint32_t)__bfloat16_as_ushort(h0l)
                            | ((uint32_t)__bfloat16_as_ushort(h1l_) << 16);
                        if (t == TT - 1)
                            *(float2*)(hlast + (size_t)row * HH + colb) =
                                make_float2(hv[rh][j][0], hv[rh][j][1]);
                    }
                }
            }

            __syncthreads();
            if (tid == 0) grp_arrive(ownG, (unsigned)(t + 1));
        }
    }
}

// ---------------------------------------------------------------------------
// out[b] = sum_k hlast[b][k] * Wd[k] + bd[0]
// ---------------------------------------------------------------------------
__global__ void dense_out_kernel(const float* __restrict__ hlast,
                                 const float* __restrict__ Wd,
                                 const float* __restrict__ bd,
                                 float* __restrict__ out)
{
    __shared__ float red[256];
    const int b = blockIdx.x;
    const int k = threadIdx.x;
    red[k] = hlast[b * HH + k] * Wd[k];
    __syncthreads();
    for (int s = 128; s > 0; s >>= 1) {
        if (k < s) red[k] += red[k + s];
        __syncthreads();
    }
    if (k == 0) out[b] = red[0] + bd[0];
}

// ---------------------------------------------------------------------------
// Launch: 6 graph nodes.
// ---------------------------------------------------------------------------
extern "C" void kernel_launch(void* const* d_in, const int* in_sizes, int n_in,
                              void* d_out, int out_size)
{
    const float* x  = (const float*)d_in[0];
    const float* W1 = (const float*)d_in[1];
    const float* U1 = (const float*)d_in[2];
    const float* b1 = (const float*)d_in[3];
    const float* W2 = (const float*)d_in[4];
    const float* U2 = (const float*)d_in[5];
    const float* b2 = (const float*)d_in[6];
    const float* Wd = (const float*)d_in[7];
    const float* bd = (const float*)d_in[8];
    float* out = (float*)d_out;

    float *xw, *z2w, *hlast;
    __nv_bfloat16 *xhi, *xlo, *h1hi, *h1lo, *h2hi, *h2lo, *whi, *wlo;
    cudaGetSymbolAddress((void**)&xw, g_xw);
    cudaGetSymbolAddress((void**)&z2w, g_z2w);
    cudaGetSymbolAddress((void**)&xhi, g_xhi);
    cudaGetSymbolAddress((void**)&xlo, g_xlo);
    cudaGetSymbolAddress((void**)&h1hi, g_h1hi);
    cudaGetSymbolAddress((void**)&h1lo, g_h1lo);
    cudaGetSymbolAddress((void**)&h2hi, g_h2hi);
    cudaGetSymbolAddress((void**)&h2lo, g_h2lo);
    cudaGetSymbolAddress((void**)&whi, g_whi);
    cudaGetSymbolAddress((void**)&wlo, g_wlo);
    cudaGetSymbolAddress((void**)&hlast, g_hlast);

    cudaFuncSetAttribute(fused_lstm_kernel,
                         cudaFuncAttributeMaxDynamicSharedMemorySize, S_TOT);

    conv_x_kernel<<<MM * 32 / 256, 256>>>(x, xhi, xlo);
    conv_w_kernel<<<FF * GG / 4 / 256, 256>>>(W1, whi, wlo);
    gemm_bf16_kernel<<<dim3(GG / 64, MM / 128), 256>>>(xhi, xlo, whi, wlo, b1, xw);
    init_flags_kernel<<<2, 256>>>();
    fused_lstm_kernel<<<128, 256, S_TOT>>>(xw, U1, W2, U2, b2, z2w,
                                           h1hi, h1lo, h2hi, h2lo, hlast);
    dense_out_kernel<<<BB, 256>>>(hlast, Wd, bd, out);
}

// round 14
// speedup vs baseline: 1.1029x; 1.1029x over previous
#include <cuda_runtime.h>
#include <cuda_bf16.h>
#include <math.h>
#include <stdint.h>

#define BB 256
#define TT 512
#define FF 256
#define HH 256
#define GG 1024
#define MM (TT * BB)

// ---------------- device globals (no runtime allocation) --------------------
__device__ __nv_bfloat16 g_xhi[(size_t)MM * FF];    // 64 MB, row m = t*B+b
__device__ __nv_bfloat16 g_xlo[(size_t)MM * FF];
__device__ __nv_bfloat16 g_h1hi[(size_t)MM * HH];   // layer-1 h sequence
__device__ __nv_bfloat16 g_h1lo[(size_t)MM * HH];
__device__ __nv_bfloat16 g_h2hi[2 * BB * HH];       // layer-2 h ring
__device__ __nv_bfloat16 g_h2lo[2 * BB * HH];
__device__ float g_hlast[BB * HH];
__device__ unsigned g_flags[8 * 32];                 // [layer*4+grp]*32

// ---------------- helpers ----------------------------------------------------
__device__ __forceinline__ float sigf(float v) { return 1.0f / (1.0f + __expf(-v)); }

__device__ __forceinline__ uint32_t smem_u32(const void* p) {
    uint32_t a;
    asm("{ .reg .u64 t; cvta.to.shared.u64 t, %1; cvt.u32.u64 %0, t; }"
        : "=r"(a) : "l"(p));
    return a;
}
__device__ __forceinline__ void ldmA(uint32_t& a0, uint32_t& a1,
                                     uint32_t& a2, uint32_t& a3, uint32_t addr) {
    asm volatile("ldmatrix.sync.aligned.m8n8.x4.shared.b16 {%0,%1,%2,%3}, [%4];"
                 : "=r"(a0), "=r"(a1), "=r"(a2), "=r"(a3) : "r"(addr));
}
__device__ __forceinline__ void ldmB(uint32_t& b0, uint32_t& b1, uint32_t addr) {
    asm volatile("ldmatrix.sync.aligned.m8n8.x2.trans.shared.b16 {%0,%1}, [%2];"
                 : "=r"(b0), "=r"(b1) : "r"(addr));
}
__device__ __forceinline__ void mma_bf16(float* d, uint32_t a0, uint32_t a1,
                                         uint32_t a2, uint32_t a3,
                                         uint32_t b0, uint32_t b1) {
    asm volatile(
        "mma.sync.aligned.m16n8k16.row.col.f32.bf16.bf16.f32 "
        "{%0,%1,%2,%3}, {%4,%5,%6,%7}, {%8,%9}, {%0,%1,%2,%3};"
        : "+f"(d[0]), "+f"(d[1]), "+f"(d[2]), "+f"(d[3])
        : "r"(a0), "r"(a1), "r"(a2), "r"(a3), "r"(b0), "r"(b1));
}
__device__ __forceinline__ void split_bf16(float v, __nv_bfloat16& hi, __nv_bfloat16& lo) {
    hi = __float2bfloat16_rn(v);
    lo = __float2bfloat16_rn(v - __bfloat162float(hi));
}
__device__ __forceinline__ void pollFlag(unsigned* f, unsigned target) {
    unsigned g;
    do {
        asm volatile("ld.acquire.gpu.u32 %0, [%1];" : "=r"(g) : "l"(f) : "memory");
    } while (g < target);
}
__device__ __forceinline__ void addFlag(unsigned* f) {
    unsigned old;
    asm volatile("atom.add.release.gpu.u32 %0, [%1], 1;"
                 : "=r"(old) : "l"(f) : "memory");
}

__global__ void init_flags_kernel() {
    if (threadIdx.x < 8 * 32) g_flags[threadIdx.x] = 0;
}

// ---------------------------------------------------------------------------
// conv_x: x[B][T][F] fp32 -> xhi/xlo bf16 rows m = t*B+b.
// ---------------------------------------------------------------------------
__global__ void conv_x_kernel(const float* __restrict__ x,
                              __nv_bfloat16* __restrict__ xhi,
                              __nv_bfloat16* __restrict__ xlo)
{
    const int gid = blockIdx.x * 256 + threadIdx.x;
    const int m = gid >> 5;
    const int c = (gid & 31) * 8;
    const int b = m & (BB - 1);
    const int t = m >> 8;
    const float* src = x + ((size_t)b * TT + t) * FF + c;
    float4 v0 = *(const float4*)src;
    float4 v1 = *(const float4*)(src + 4);
    float vv[8] = {v0.x, v0.y, v0.z, v0.w, v1.x, v1.y, v1.z, v1.w};
    __nv_bfloat16 hi8[8], lo8[8];
#pragma unroll
    for (int j = 0; j < 8; j++) split_bf16(vv[j], hi8[j], lo8[j]);
    *(uint4*)(xhi + (size_t)m * FF + c) = *(uint4*)hi8;
    *(uint4*)(xlo + (size_t)m * FF + c) = *(uint4*)lo8;
}

// ---------------------------------------------------------------------------
// Fused 2-layer pipelined LSTM. 128 CTAs x 256 thr.
// bid<64: layer 1 (4 grps x 16 CTAs); bid>=64: layer 2.
// CTA tile: 64 batch rows x (4 gates x 16 hc). Per step:
//   poll flags -> reg-prefetch W operand (x(t)/h1(t)) -> stage h(t-1) ->
//   MMA U pass -> STS regs -> MMA W pass -> epilogue.
// bf16 hi/lo split (3 MMA terms, merged accumulator), fp32 accum.
// smem = 207872 B (identical to R9 layout).
// ---------------------------------------------------------------------------
#define SA_STR 528
#define S_AHI 0
#define S_ALO 33792
#define S_BWH 67584
#define S_BWL 100352
#define S_BUH 133120
#define S_BUL 165888
#define S_Z   198656
#define ZST   36
#define S_TOT (S_Z + 64 * ZST * 4)
#define BL_OFF 32768

// Merged-acc pass: 3 split terms into one acc set.
__device__ __forceinline__ void mma_pass(float acc[2][2][4],
                                         uint32_t aHi, uint32_t aLo,
                                         uint32_t bBase)
{
#pragma unroll
    for (int kc = 0; kc < 16; kc++) {
        uint32_t ah0, ah1, ah2, ah3, al0, al1, al2, al3;
        ldmA(ah0, ah1, ah2, ah3, aHi + kc * 32);
        ldmA(al0, al1, al2, al3, aLo + kc * 32);
#pragma unroll
        for (int gl = 0; gl < 2; gl++) {
#pragma unroll
            for (int j = 0; j < 2; j++) {
                const uint32_t b = bBase + gl * 8192 + j * 16 + kc * 512;
                uint32_t bh0, bh1, bl0, bl1;
                ldmB(bh0, bh1, b);
                ldmB(bl0, bl1, b + BL_OFF);
                mma_bf16(acc[gl][j], ah0, ah1, ah2, ah3, bh0, bh1);
                mma_bf16(acc[gl][j], ah0, ah1, ah2, ah3, bl0, bl1);
                mma_bf16(acc[gl][j], al0, al1, al2, al3, bh0, bh1);
            }
        }
    }
}

__global__ void __launch_bounds__(256, 1)
fused_lstm_kernel(const __nv_bfloat16* __restrict__ xhi,
                  const __nv_bfloat16* __restrict__ xlo,
                  const float* __restrict__ W1, const float* __restrict__ U1,
                  const float* __restrict__ b1,
                  const float* __restrict__ W2, const float* __restrict__ U2,
                  const float* __restrict__ b2,
                  __nv_bfloat16* __restrict__ h1hi,
                  __nv_bfloat16* __restrict__ h1lo,
                  __nv_bfloat16* __restrict__ h2hi,
                  __nv_bfloat16* __restrict__ h2lo,
                  float* __restrict__ hlast)
{
    extern __shared__ char smem[];
    const uint32_t sb = smem_u32(smem);
    float* zs = (float*)(smem + S_Z);

    const int tid  = threadIdx.x;
    const int w    = tid >> 5;
    const int lane = tid & 31;
    const int layer = blockIdx.x >> 6;
    const int sub   = blockIdx.x & 63;
    const int grp   = sub >> 4;
    const int gm0   = grp * 64;
    const int hc0   = (sub & 15) * 16;
    const int msub  = w & 3;
    const int gp    = w >> 2;         // 0: gates i,f (epilogue); 1: gates g,o
    const int isEpi = (gp == 0);

    const float* Wsrc = layer ? W2 : W1;
    const float* Usrc = layer ? U2 : U1;
    const float* bsrc = layer ? b2 : b1;
    unsigned* ownFlag = &g_flags[(layer * 4 + grp) * 32];
    unsigned* l1Flag  = &g_flags[grp * 32];

    // ---- one-time B fills: W and U slices, bf16 hi/lo, [gate][k][16 hc] ----
    for (int i = tid; i < 4 * 256 * 2; i += 256) {
        const int g = i >> 9;
        const int k = (i >> 1) & 255;
        const int half = i & 1;
        const int co = g * HH + hc0 + half * 8;
        const uint32_t so = (uint32_t)(g * 8192 + k * 32 + half * 16);
        {
            const float* src = Wsrc + (size_t)k * GG + co;
            __nv_bfloat16 h8[8], l8[8];
#pragma unroll
            for (int j = 0; j < 8; j++) split_bf16(src[j], h8[j], l8[j]);
            *(uint4*)(smem + S_BWH + so) = *(uint4*)h8;
            *(uint4*)(smem + S_BWL + so) = *(uint4*)l8;
        }
        {
            const float* src = Usrc + (size_t)k * GG + co;
            __nv_bfloat16 h8[8], l8[8];
#pragma unroll
            for (int j = 0; j < 8; j++) split_bf16(src[j], h8[j], l8[j]);
            *(uint4*)(smem + S_BUH + so) = *(uint4*)h8;
            *(uint4*)(smem + S_BUL + so) = *(uint4*)l8;
        }
    }

    // fragment-native ownership (epilogue warps)
    const int r0 = msub * 16 + (lane >> 2);
    const int c  = (lane & 3) * 2;
    float biaf[4][2][2];
    if (isEpi) {
#pragma unroll
        for (int g = 0; g < 4; g++)
#pragma unroll
            for (int j = 0; j < 2; j++) {
                const float2 bb = *(const float2*)(bsrc + g * HH + hc0 + j * 8 + c);
                biaf[g][j][0] = bb.x;
                biaf[g][j][1] = bb.y;
            }
    }
    float creg[8];
#pragma unroll
    for (int i = 0; i < 8; i++) creg[i] = 0.f;

    const uint32_t aBase = (uint32_t)((msub * 16 + (lane & 15)) * SA_STR
                                      + (lane >> 4) * 16);
    const uint32_t aHi = sb + S_AHI + aBase;
    const uint32_t aLo = sb + S_ALO + aBase;
    const uint32_t bW = sb + S_BWH + gp * 2 * 8192 + (lane & 15) * 32;
    const uint32_t bU = sb + S_BUH + gp * 2 * 8192 + (lane & 15) * 32;

    const __nv_bfloat16* wsrc_hi = layer ? h1hi : xhi;
    const __nv_bfloat16* wsrc_lo = layer ? h1lo : xlo;

    for (int t = 0; t < TT; t++) {
        const int doU = (t > 0);

        // ---- 1. merged polls ----
        if (tid == 0) {
            if (layer) pollFlag(l1Flag, 16u * (unsigned)(t + 1));
            if (doU)   pollFlag(ownFlag, 16u * (unsigned)t);
        }
        __syncthreads();

        // ---- 2. reg-prefetch W-pass operand (x(t) / h1(t)): in flight
        //         through staging + U MMA ----
        uint4 pregh[8], pregl[8];
        {
            const size_t rowb = (size_t)t * BB + gm0;
#pragma unroll
            for (int i = 0; i < 8; i++) {
                const int id = tid + i * 256;
                const int r  = id >> 5;
                const int cc = id & 31;
                pregh[i] = *((const uint4*)(wsrc_hi + (rowb + r) * 256) + cc);
                pregl[i] = *((const uint4*)(wsrc_lo + (rowb + r) * 256) + cc);
            }
        }

        float accW[2][2][4], accU[2][2][4];
#pragma unroll
        for (int gl = 0; gl < 2; gl++)
#pragma unroll
            for (int j = 0; j < 2; j++)
#pragma unroll
                for (int q = 0; q < 4; q++) {
                    accW[gl][j][q] = 0.f;
                    accU[gl][j][q] = 0.f;
                }

        // ---- 3. stage h(t-1), U pass ----
        if (doU) {
            if (layer == 0) {
                const size_t rowb = (size_t)(t - 1) * BB + gm0;
#pragma unroll
                for (int i = 0; i < 8; i++) {
                    const int id = tid + i * 256;
                    const int r  = id >> 5;
                    const int cc = id & 31;
                    const uint4 vh = *((const uint4*)(h1hi + (rowb + r) * HH) + cc);
                    const uint4 vl = *((const uint4*)(h1lo + (rowb + r) * HH) + cc);
                    *(uint4*)(smem + S_AHI + r * SA_STR + cc * 16) = vh;
                    *(uint4*)(smem + S_ALO + r * SA_STR + cc * 16) = vl;
                }
            } else {
                const __nv_bfloat16* shi = h2hi + (size_t)((t - 1) & 1) * BB * HH;
                const __nv_bfloat16* slo = h2lo + (size_t)((t - 1) & 1) * BB * HH;
#pragma unroll
                for (int i = 0; i < 8; i++) {
                    const int id = tid + i * 256;
                    const int r  = id >> 5;
                    const int cc = id & 31;
                    const uint4 vh = *((const uint4*)(shi + (size_t)(gm0 + r) * HH) + cc);
                    const uint4 vl = *((const uint4*)(slo + (size_t)(gm0 + r) * HH) + cc);
                    *(uint4*)(smem + S_AHI + r * SA_STR + cc * 16) = vh;
                    *(uint4*)(smem + S_ALO + r * SA_STR + cc * 16) = vl;
                }
            }
            __syncthreads();
            mma_pass(accU, aHi, aLo, bU);
            __syncthreads();   // all U-MMA reads of A done before overwrite
        }

        // ---- 4. STS prefetched regs, W pass ----
#pragma unroll
        for (int i = 0; i < 8; i++) {
            const int id = tid + i * 256;
            const int r  = id >> 5;
            const int cc = id & 31;
            *(uint4*)(smem + S_AHI + r * SA_STR + cc * 16) = pregh[i];
            *(uint4*)(smem + S_ALO + r * SA_STR + cc * 16) = pregl[i];
        }
        __syncthreads();
        mma_pass(accW, aHi, aLo, bW);

        // ---- 5. epilogue ----
        float v[2][2][4];
#pragma unroll
        for (int gl = 0; gl < 2; gl++)
#pragma unroll
            for (int j = 0; j < 2; j++)
#pragma unroll
                for (int q = 0; q < 4; q++)
                    v[gl][j][q] = accW[gl][j][q] + accU[gl][j][q];

        if (!isEpi) {
#pragma unroll
            for (int gl = 0; gl < 2; gl++)
#pragma unroll
                for (int j = 0; j < 2; j++) {
                    *(float2*)&zs[r0 * ZST + gl * 16 + j * 8 + c] =
                        make_float2(v[gl][j][0], v[gl][j][1]);
                    *(float2*)&zs[(r0 + 8) * ZST + gl * 16 + j * 8 + c] =
                        make_float2(v[gl][j][2], v[gl][j][3]);
                }
        }
        asm volatile("bar.sync %0, 64;" :: "r"(1 + msub) : "memory");

        if (isEpi) {
            float zgv[2][2][2], zov[2][2][2];
#pragma unroll
            for (int j = 0; j < 2; j++)
#pragma unroll
                for (int rh = 0; rh < 2; rh++) {
                    const float2 a = *(float2*)&zs[(r0 + rh * 8) * ZST + 0 + j * 8 + c];
                    const float2 b = *(float2*)&zs[(r0 + rh * 8) * ZST + 16 + j * 8 + c];
                    zgv[j][rh][0] = a.x; zgv[j][rh][1] = a.y;
                    zov[j][rh][0] = b.x; zov[j][rh][1] = b.y;
                }
            float hv[2][2][2];
#pragma unroll
            for (int rh = 0; rh < 2; rh++)
#pragma unroll
                for (int j = 0; j < 2; j++)
#pragma unroll
                    for (int cp = 0; cp < 2; cp++) {
                        const int q = rh * 2 + cp;
                        const float zi = v[0][j][q]     + biaf[0][j][cp];
                        const float zf = v[1][j][q]     + biaf[1][j][cp];
                        const float zg = zgv[j][rh][cp] + biaf[2][j][cp];
                        const float zo = zov[j][rh][cp] + biaf[3][j][cp];
                        const float ig = sigf(zi), fg = sigf(zf);
                        const float gg = __tanhf(zg), og = sigf(zo);
                        const int ci = rh * 4 + j * 2 + cp;
                        const float cn = fg * creg[ci] + ig * gg;
                        creg[ci] = cn;
                        hv[rh][j][cp] = og * __tanhf(cn);
                    }

#pragma unroll
            for (int rh = 0; rh < 2; rh++) {
                const int row = gm0 + r0 + rh * 8;
#pragma unroll
                for (int j = 0; j < 2; j++) {
                    const int colb = hc0 + j * 8 + c;
                    __nv_bfloat16 h0h, h1h_, h0l, h1l_;
                    split_bf16(hv[rh][j][0], h0h, h0l);
                    split_bf16(hv[rh][j][1], h1h_, h1l_);
                    const uint32_t phi = (uint32_t)__bfloat16_as_ushort(h0h)
                                       | ((uint32_t)__bfloat16_as_ushort(h1h_) << 16);
                    const uint32_t plo = (uint32_t)__bfloat16_as_ushort(h0l)
                                       | ((uint32_t)__bfloat16_as_ushort(h1l_) << 16);
                    if (layer == 0) {
                        const size_t off = ((size_t)t * BB + row) * HH + colb;
                        *(uint32_t*)(h1hi + off) = phi;
                        *(uint32_t*)(h1lo + off) = plo;
                    } else {
                        const size_t off = (size_t)(t & 1) * BB * HH
                                         + (size_t)row * HH + colb;
                        *(uint32_t*)(h2hi + off) = phi;
                        *(uint32_t*)(h2lo + off) = plo;
                        if (t == TT - 1)
                            *(float2*)(hlast + (size_t)row * HH + colb) =
                                make_float2(hv[rh][j][0], hv[rh][j][1]);
                    }
                }
            }
        }

        __syncthreads();
        if (tid == 0) addFlag(ownFlag);
    }
}

// ---------------------------------------------------------------------------
// out[b] = sum_k hlast[b][k] * Wd[k] + bd[0]
// ---------------------------------------------------------------------------
__global__ void dense_out_kernel(const float* __restrict__ hlast,
                                 const float* __restrict__ Wd,
                                 const float* __restrict__ bd,
                                 float* __restrict__ out)
{
    __shared__ float red[256];
    const int b = blockIdx.x;
    const int k = threadIdx.x;
    red[k] = hlast[b * HH + k] * Wd[k];
    __syncthreads();
    for (int s = 128; s > 0; s >>= 1) {
        if (k < s) red[k] += red[k + s];
        __syncthreads();
    }
    if (k == 0) out[b] = red[0] + bd[0];
}

// ---------------------------------------------------------------------------
// Launch: 4 graph nodes.
// ---------------------------------------------------------------------------
extern "C" void kernel_launch(void* const* d_in, const int* in_sizes, int n_in,
                              void* d_out, int out_size)
{
    const float* x  = (const float*)d_in[0];
    const float* W1 = (const float*)d_in[1];
    const float* U1 = (const float*)d_in[2];
    const float* b1 = (const float*)d_in[3];
    const float* W2 = (const float*)d_in[4];
    const float* U2 = (const float*)d_in[5];
    const float* b2 = (const float*)d_in[6];
    const float* Wd = (const float*)d_in[7];
    const float* bd = (const float*)d_in[8];
    float* out = (float*)d_out;

    float* hlast;
    __nv_bfloat16 *xhi, *xlo, *h1hi, *h1lo, *h2hi, *h2lo;
    cudaGetSymbolAddress((void**)&xhi, g_xhi);
    cudaGetSymbolAddress((void**)&xlo, g_xlo);
    cudaGetSymbolAddress((void**)&h1hi, g_h1hi);
    cudaGetSymbolAddress((void**)&h1lo, g_h1lo);
    cudaGetSymbolAddress((void**)&h2hi, g_h2hi);
    cudaGetSymbolAddress((void**)&h2lo, g_h2lo);
    cudaGetSymbolAddress((void**)&hlast, g_hlast);

    cudaFuncSetAttribute(fused_lstm_kernel,
                         cudaFuncAttributeMaxDynamicSharedMemorySize, S_TOT);

    conv_x_kernel<<<MM * 32 / 256, 256>>>(x, xhi, xlo);
    init_flags_kernel<<<1, 256>>>();
    fused_lstm_kernel<<<128, 256, S_TOT>>>(xhi, xlo, W1, U1, b1, W2, U2, b2,
                                           h1hi, h1lo, h2hi, h2lo, hlast);
    dense_out_kernel<<<BB, 256>>>(hlast, Wd, bd, out);
}